// round 3
// baseline (speedup 1.0000x reference)
#include <cuda_runtime.h>
#include <cuda_fp16.h>
#include <cstdint>

// ============================================================================
// Int8Linear: y[M,N] = (x[M,K] @ W^T[K,N]) * scale[n], fp32 accum
// M = B*S = 4096, K = 4096, N = 11008
//
// Harness dtype canonicalization (supported set: f32 / int32 / bf16):
//   x      : float16 -> float32   (const float*)
//   weight : int8    -> int32     (const int*)      <-- round-2 bug was here
//   scale  : float32              (const float*)
//   y      : float16 -> float32   (float*), round through f16 before store
//
// Stage 1: convert x f32->f16 and W int32->f16 (both exact) into scratch.
// Stage 2: pipelined mma.sync.m16n8k16 fp16 GEMM, scale in epilogue.
// ============================================================================

#define BM 128
#define BN 128
#define BK 32
#define STAGES 4
#define LDT 40            // padded smem row pitch in halves (80 B)
#define THREADS 256

#define N_MAX 11008
#define K_FIXED 4096
#define M_MAX 4096

// Scratch (sanctioned __device__ globals): 90MB W + 34MB x
__device__ __half g_wh[(size_t)N_MAX * K_FIXED];
__device__ __half g_xh[(size_t)M_MAX * K_FIXED];

// ---------------------------------------------------------------------------
// W int32 -> fp16 (exact: |w| <= 127)
// ---------------------------------------------------------------------------
__global__ void convert_w_kernel(const int* __restrict__ w,
                                 __half* __restrict__ out, int n8) {
    int i = blockIdx.x * blockDim.x + threadIdx.x;
    if (i >= n8) return;
    int4 a = reinterpret_cast<const int4*>(w)[2 * i];
    int4 b = reinterpret_cast<const int4*>(w)[2 * i + 1];
    __half h[8];
    h[0] = __int2half_rn(a.x); h[1] = __int2half_rn(a.y);
    h[2] = __int2half_rn(a.z); h[3] = __int2half_rn(a.w);
    h[4] = __int2half_rn(b.x); h[5] = __int2half_rn(b.y);
    h[6] = __int2half_rn(b.z); h[7] = __int2half_rn(b.w);
    reinterpret_cast<uint4*>(out)[i] = *reinterpret_cast<uint4*>(h);
}

// ---------------------------------------------------------------------------
// x f32 -> f16 (exact: values were originally f16)
// ---------------------------------------------------------------------------
__global__ void convert_x_kernel(const float* __restrict__ x,
                                 __half* __restrict__ out, int n8) {
    int i = blockIdx.x * blockDim.x + threadIdx.x;
    if (i >= n8) return;
    float4 a = reinterpret_cast<const float4*>(x)[2 * i];
    float4 b = reinterpret_cast<const float4*>(x)[2 * i + 1];
    __half h[8];
    h[0] = __float2half_rn(a.x); h[1] = __float2half_rn(a.y);
    h[2] = __float2half_rn(a.z); h[3] = __float2half_rn(a.w);
    h[4] = __float2half_rn(b.x); h[5] = __float2half_rn(b.y);
    h[6] = __float2half_rn(b.z); h[7] = __float2half_rn(b.w);
    reinterpret_cast<uint4*>(out)[i] = *reinterpret_cast<uint4*>(h);
}

// ---------------------------------------------------------------------------
// PTX helpers
// ---------------------------------------------------------------------------
__device__ __forceinline__ uint32_t smem_u32(const void* p) {
    return (uint32_t)__cvta_generic_to_shared(p);
}

__device__ __forceinline__ void cp_async16(uint32_t s, const void* g) {
    asm volatile("cp.async.cg.shared.global [%0], [%1], 16;\n" ::"r"(s), "l"(g));
}

__device__ __forceinline__ void ldsm4(uint32_t r[4], uint32_t addr) {
    asm volatile("ldmatrix.sync.aligned.m8n8.x4.shared.b16 {%0,%1,%2,%3}, [%4];\n"
                 : "=r"(r[0]), "=r"(r[1]), "=r"(r[2]), "=r"(r[3])
                 : "r"(addr));
}

__device__ __forceinline__ void ldsm2(uint32_t r[2], uint32_t addr) {
    asm volatile("ldmatrix.sync.aligned.m8n8.x2.shared.b16 {%0,%1}, [%2];\n"
                 : "=r"(r[0]), "=r"(r[1])
                 : "r"(addr));
}

__device__ __forceinline__ void mma_16816(float c[4], const uint32_t a[4],
                                          const uint32_t b[2]) {
    asm volatile(
        "mma.sync.aligned.m16n8k16.row.col.f32.f16.f16.f32 "
        "{%0,%1,%2,%3}, {%4,%5,%6,%7}, {%8,%9}, {%0,%1,%2,%3};\n"
        : "+f"(c[0]), "+f"(c[1]), "+f"(c[2]), "+f"(c[3])
        : "r"(a[0]), "r"(a[1]), "r"(a[2]), "r"(a[3]), "r"(b[0]), "r"(b[1]));
}

// ---------------------------------------------------------------------------
// cp.async tile loader: 128x32 halves per operand, 2 x 16B chunks per thread
// ---------------------------------------------------------------------------
__device__ __forceinline__ void load_tile(__half* As, __half* Bs,
                                          const __half* Ag, const __half* Bg,
                                          int k0, int K, int tid) {
#pragma unroll
    for (int i = 0; i < 2; ++i) {
        int c = tid + i * THREADS;      // 0..511
        int row = c >> 2;               // 0..127
        int col = (c & 3) << 3;         // 0,8,16,24
        cp_async16(smem_u32(As + row * LDT + col),
                   Ag + (size_t)row * K + k0 + col);
        cp_async16(smem_u32(Bs + row * LDT + col),
                   Bg + (size_t)row * K + k0 + col);
    }
}

// ---------------------------------------------------------------------------
// GEMM: grid.x = M tiles (fast-varying -> B-tile multicast via L2)
// ---------------------------------------------------------------------------
__global__ void __launch_bounds__(THREADS, 2)
gemm_f16_kernel(const __half* __restrict__ A, const __half* __restrict__ Bw,
                const float* __restrict__ scale, float* __restrict__ C,
                int M, int N, int K) {
    extern __shared__ __half smem[];
    __half* As = smem;                            // STAGES * BM * LDT
    __half* Bs = smem + STAGES * BM * LDT;        // STAGES * BN * LDT

    const int tid = threadIdx.x;
    const int lane = tid & 31;
    const int warp = tid >> 5;
    const int warp_m = warp >> 2;  // 0..1 (64 rows each)
    const int warp_n = warp & 3;   // 0..3 (32 cols each)

    const int bm = blockIdx.x * BM;
    const int bn = blockIdx.y * BN;

    const __half* Ag = A + (size_t)bm * K;
    const __half* Bg = Bw + (size_t)bn * K;

    float acc[4][4][4];
#pragma unroll
    for (int i = 0; i < 4; ++i)
#pragma unroll
        for (int j = 0; j < 4; ++j)
#pragma unroll
            for (int v = 0; v < 4; ++v) acc[i][j][v] = 0.0f;

    const int KITERS = K / BK;  // 128

#pragma unroll
    for (int s = 0; s < STAGES - 1; ++s) {
        load_tile(As + s * BM * LDT, Bs + s * BN * LDT, Ag, Bg, s * BK, K, tid);
        asm volatile("cp.async.commit_group;\n");
    }

    const int a_row = lane & 15;
    const int a_k   = (lane >> 4) << 3;
    const int b_row = lane & 7;
    const int b_k   = ((lane >> 3) & 1) << 3;

    for (int it = 0; it < KITERS; ++it) {
        asm volatile("cp.async.wait_group %0;\n" ::"n"(STAGES - 2));
        __syncthreads();

        int nxt = it + STAGES - 1;
        if (nxt < KITERS) {
            int ns = nxt % STAGES;
            load_tile(As + ns * BM * LDT, Bs + ns * BN * LDT, Ag, Bg,
                      nxt * BK, K, tid);
        }
        asm volatile("cp.async.commit_group;\n");

        const int st = it % STAGES;
        const __half* Ast = As + st * BM * LDT;
        const __half* Bst = Bs + st * BN * LDT;

#pragma unroll
        for (int ks = 0; ks < 2; ++ks) {
            uint32_t af[4][4], bf[4][2];
#pragma unroll
            for (int tm = 0; tm < 4; ++tm) {
                int row = warp_m * 64 + tm * 16 + a_row;
                ldsm4(af[tm], smem_u32(Ast + row * LDT + ks * 16 + a_k));
            }
#pragma unroll
            for (int tn = 0; tn < 4; ++tn) {
                int row = warp_n * 32 + tn * 8 + b_row;
                ldsm2(bf[tn], smem_u32(Bst + row * LDT + ks * 16 + b_k));
            }
#pragma unroll
            for (int tm = 0; tm < 4; ++tm)
#pragma unroll
                for (int tn = 0; tn < 4; ++tn)
                    mma_16816(acc[tm][tn], af[tm], bf[tn]);
        }
    }

    // Epilogue: scale, round through f16 (matches reference .astype(float16)),
    // store as f32 pairs.
    const int c_row = lane >> 2;
    const int c_col = (lane & 3) << 1;

#pragma unroll
    for (int tm = 0; tm < 4; ++tm) {
#pragma unroll
        for (int tn = 0; tn < 4; ++tn) {
            int n = bn + warp_n * 32 + tn * 8 + c_col;
            float s0 = __ldg(scale + n);
            float s1 = __ldg(scale + n + 1);
            int m0 = bm + warp_m * 64 + tm * 16 + c_row;
            float2 r0, r1;
            r0.x = __half2float(__float2half_rn(acc[tm][tn][0] * s0));
            r0.y = __half2float(__float2half_rn(acc[tm][tn][1] * s1));
            r1.x = __half2float(__float2half_rn(acc[tm][tn][2] * s0));
            r1.y = __half2float(__float2half_rn(acc[tm][tn][3] * s1));
            *reinterpret_cast<float2*>(&C[(size_t)m0 * N + n]) = r0;
            *reinterpret_cast<float2*>(&C[(size_t)(m0 + 8) * N + n]) = r1;
        }
    }
}

// ---------------------------------------------------------------------------
// kernel_launch
// ---------------------------------------------------------------------------
extern "C" void kernel_launch(void* const* d_in, const int* in_sizes, int n_in,
                              void* d_out, int out_size) {
    const float* x = (const float*)d_in[0];
    const int* w32 = (const int*)d_in[1];      // int8 widened to int32
    const float* scale = (const float*)d_in[2];
    float* y = (float*)d_out;

    const int K = K_FIXED;
    const int N = in_sizes[2];           // 11008
    const int M = in_sizes[0] / K;       // 4096

    __half* wh = nullptr;
    cudaGetSymbolAddress((void**)&wh, g_wh);
    __half* xh = nullptr;
    cudaGetSymbolAddress((void**)&xh, g_xh);

    // Stage 1: exact dtype conversions
    int nw8 = (N * K) / 8;
    convert_w_kernel<<<(nw8 + 255) / 256, 256>>>(w32, wh, nw8);
    int nx8 = (M * K) / 8;
    convert_x_kernel<<<(nx8 + 255) / 256, 256>>>(x, xh, nx8);

    // Stage 2: GEMM
    size_t smem_bytes = (size_t)STAGES * (BM + BN) * LDT * sizeof(__half);
    cudaFuncSetAttribute(gemm_f16_kernel,
                         cudaFuncAttributeMaxDynamicSharedMemorySize,
                         (int)smem_bytes);

    dim3 grid(M / BM, N / BN);   // M fastest -> A resident in L2
    gemm_f16_kernel<<<grid, THREADS, smem_bytes>>>(xh, wh, scale, y, M, N, K);
}

// round 5
// speedup vs baseline: 1.1991x; 1.1991x over previous
#include <cuda_runtime.h>
#include <cuda_fp16.h>
#include <cstdint>

// ============================================================================
// Int8Linear: y[M,N] = (x[M,K] @ W^T[K,N]) * scale[n], fp32 accum
// M=4096, K=4096, N=11008.
// compute_103 feature set only (no tcgen05/TMA-tensor at this PTX target):
// mma.sync.m16n8k16 + cp.async, 128x128x64 tile, 3-stage ring, XOR-128
// swizzled smem (no padding), 2 CTAs/SM.
// ============================================================================

#define BM 128
#define BN 128
#define BK 64              // halves per stage chunk; 64 h = 128 B row
#define STAGES 3
#define THREADS 256

#define STAGE_BYTES 32768  // A 16KB + B 16KB
#define SMEM_TOTAL (STAGES * STAGE_BYTES)  // 96 KB

#define N_MAX 11008
#define K_FIXED 4096
#define M_MAX 4096

__device__ __half g_wh[(size_t)N_MAX * K_FIXED];
__device__ __half g_xh[(size_t)M_MAX * K_FIXED];

// ---------------------------------------------------------------------------
// W int32 -> fp16 (exact: |w| <= 127)
// ---------------------------------------------------------------------------
__global__ void convert_w_kernel(const int* __restrict__ w,
                                 __half* __restrict__ out, int n8) {
    int i = blockIdx.x * blockDim.x + threadIdx.x;
    if (i >= n8) return;
    int4 a = reinterpret_cast<const int4*>(w)[2 * i];
    int4 b = reinterpret_cast<const int4*>(w)[2 * i + 1];
    __half h[8];
    h[0] = __int2half_rn(a.x); h[1] = __int2half_rn(a.y);
    h[2] = __int2half_rn(a.z); h[3] = __int2half_rn(a.w);
    h[4] = __int2half_rn(b.x); h[5] = __int2half_rn(b.y);
    h[6] = __int2half_rn(b.z); h[7] = __int2half_rn(b.w);
    reinterpret_cast<uint4*>(out)[i] = *reinterpret_cast<uint4*>(h);
}

// ---------------------------------------------------------------------------
// x f32 -> f16 (exact: values were originally f16)
// ---------------------------------------------------------------------------
__global__ void convert_x_kernel(const float* __restrict__ x,
                                 __half* __restrict__ out, int n8) {
    int i = blockIdx.x * blockDim.x + threadIdx.x;
    if (i >= n8) return;
    float4 a = reinterpret_cast<const float4*>(x)[2 * i];
    float4 b = reinterpret_cast<const float4*>(x)[2 * i + 1];
    __half h[8];
    h[0] = __float2half_rn(a.x); h[1] = __float2half_rn(a.y);
    h[2] = __float2half_rn(a.z); h[3] = __float2half_rn(a.w);
    h[4] = __float2half_rn(b.x); h[5] = __float2half_rn(b.y);
    h[6] = __float2half_rn(b.z); h[7] = __float2half_rn(b.w);
    reinterpret_cast<uint4*>(out)[i] = *reinterpret_cast<uint4*>(h);
}

// ---------------------------------------------------------------------------
// PTX helpers
// ---------------------------------------------------------------------------
__device__ __forceinline__ uint32_t smem_u32(const void* p) {
    return (uint32_t)__cvta_generic_to_shared(p);
}

__device__ __forceinline__ uint32_t sw128(uint32_t off) {
    return off ^ ((off >> 3) & 0x70);
}

__device__ __forceinline__ void cp_async16(uint32_t s, const void* g) {
    asm volatile("cp.async.cg.shared.global [%0], [%1], 16;\n" ::"r"(s), "l"(g));
}

__device__ __forceinline__ void ldsm4(uint32_t r[4], uint32_t addr) {
    asm volatile("ldmatrix.sync.aligned.m8n8.x4.shared.b16 {%0,%1,%2,%3}, [%4];\n"
                 : "=r"(r[0]), "=r"(r[1]), "=r"(r[2]), "=r"(r[3])
                 : "r"(addr));
}

__device__ __forceinline__ void ldsm2(uint32_t r[2], uint32_t addr) {
    asm volatile("ldmatrix.sync.aligned.m8n8.x2.shared.b16 {%0,%1}, [%2];\n"
                 : "=r"(r[0]), "=r"(r[1])
                 : "r"(addr));
}

__device__ __forceinline__ void mma_16816(float c[4], const uint32_t a[4],
                                          const uint32_t b[2]) {
    asm volatile(
        "mma.sync.aligned.m16n8k16.row.col.f32.f16.f16.f32 "
        "{%0,%1,%2,%3}, {%4,%5,%6,%7}, {%8,%9}, {%0,%1,%2,%3};\n"
        : "+f"(c[0]), "+f"(c[1]), "+f"(c[2]), "+f"(c[3])
        : "r"(a[0]), "r"(a[1]), "r"(a[2]), "r"(a[3]), "r"(b[0]), "r"(b[1]));
}

// ---------------------------------------------------------------------------
// Stage loader: A 128x64h + B 128x64h, XOR-128 swizzle, 4 chunks/thread/op
// ---------------------------------------------------------------------------
__device__ __forceinline__ void load_stage(uint32_t baseA, uint32_t baseB,
                                           const __half* __restrict__ Ag,
                                           const __half* __restrict__ Bg,
                                           int K, int k0, int tid) {
#pragma unroll
    for (int t = 0; t < 4; ++t) {
        int ch = tid + t * THREADS;   // 0..1023
        int row = ch >> 3;            // 0..127
        int c16 = ch & 7;             // 16B chunk in 128B row
        uint32_t sw = sw128((uint32_t)(row * 128 + c16 * 16));
        cp_async16(baseA + sw, Ag + (size_t)row * K + k0 + c16 * 8);
        cp_async16(baseB + sw, Bg + (size_t)row * K + k0 + c16 * 8);
    }
}

// ---------------------------------------------------------------------------
// GEMM
// ---------------------------------------------------------------------------
__global__ void __launch_bounds__(THREADS, 2)
gemm_f16_kernel(const __half* __restrict__ A, const __half* __restrict__ Bw,
                const float* __restrict__ scale, float* __restrict__ C,
                int M, int N, int K) {
    extern __shared__ char smem[];
    const uint32_t sb = smem_u32(smem);

    const int tid = threadIdx.x;
    const int lane = tid & 31;
    const int warp = tid >> 5;
    const int warp_m = warp >> 2;  // 0..1 (64 rows)
    const int warp_n = warp & 3;   // 0..3 (32 cols)

    const int bm = blockIdx.x * BM;
    const int bn = blockIdx.y * BN;

    const __half* Ag = A + (size_t)bm * K;
    const __half* Bg = Bw + (size_t)bn * K;

    float acc[4][4][4];
#pragma unroll
    for (int i = 0; i < 4; ++i)
#pragma unroll
        for (int j = 0; j < 4; ++j)
#pragma unroll
            for (int v = 0; v < 4; ++v) acc[i][j][v] = 0.0f;

    const int KITERS = K / BK;  // 64

    // Prologue: stages 0,1
#pragma unroll
    for (int s = 0; s < STAGES - 1; ++s) {
        load_stage(sb + s * STAGE_BYTES, sb + s * STAGE_BYTES + 16384, Ag, Bg,
                   K, s * BK, tid);
        asm volatile("cp.async.commit_group;\n");
    }

    // ldmatrix lane addressing (same mapping validated in R3)
    const int a_row = lane & 15;              // row within 16
    const int a_kb  = (lane >> 4) << 4;       // 0 or 16 bytes
    const int b_row = lane & 7;               // row within 8
    const int b_kb  = ((lane >> 3) & 1) << 4; // 0 or 16 bytes

    for (int it = 0; it < KITERS; ++it) {
        int nxt = it + STAGES - 1;
        if (nxt < KITERS) {
            int ns = nxt % STAGES;
            load_stage(sb + ns * STAGE_BYTES, sb + ns * STAGE_BYTES + 16384,
                       Ag, Bg, K, nxt * BK, tid);
        }
        asm volatile("cp.async.commit_group;\n");
        asm volatile("cp.async.wait_group %0;\n" ::"n"(STAGES - 1));
        __syncthreads();

        const uint32_t Ast = sb + (it % STAGES) * STAGE_BYTES;
        const uint32_t Bst = Ast + 16384;

#pragma unroll
        for (int ks = 0; ks < 4; ++ks) {  // four k16 steps per BK=64
            uint32_t af[4][4], bf[4][2];
#pragma unroll
            for (int tm = 0; tm < 4; ++tm) {
                uint32_t off = (uint32_t)((warp_m * 64 + tm * 16 + a_row) * 128
                                          + ks * 32 + a_kb);
                ldsm4(af[tm], Ast + sw128(off));
            }
#pragma unroll
            for (int tn = 0; tn < 4; ++tn) {
                uint32_t off = (uint32_t)((warp_n * 32 + tn * 8 + b_row) * 128
                                          + ks * 32 + b_kb);
                ldsm2(bf[tn], Bst + sw128(off));
            }
#pragma unroll
            for (int tm = 0; tm < 4; ++tm)
#pragma unroll
                for (int tn = 0; tn < 4; ++tn)
                    mma_16816(acc[tm][tn], af[tm], bf[tn]);
        }
        __syncthreads();
    }

    // Epilogue: scale, round through f16, f32 pair stores
    const int c_row = lane >> 2;
    const int c_col = (lane & 3) << 1;

#pragma unroll
    for (int tm = 0; tm < 4; ++tm) {
#pragma unroll
        for (int tn = 0; tn < 4; ++tn) {
            int n = bn + warp_n * 32 + tn * 8 + c_col;
            float s0 = __ldg(scale + n);
            float s1 = __ldg(scale + n + 1);
            int m0 = bm + warp_m * 64 + tm * 16 + c_row;
            float2 r0, r1;
            r0.x = __half2float(__float2half_rn(acc[tm][tn][0] * s0));
            r0.y = __half2float(__float2half_rn(acc[tm][tn][1] * s1));
            r1.x = __half2float(__float2half_rn(acc[tm][tn][2] * s0));
            r1.y = __half2float(__float2half_rn(acc[tm][tn][3] * s1));
            *reinterpret_cast<float2*>(&C[(size_t)m0 * N + n]) = r0;
            *reinterpret_cast<float2*>(&C[(size_t)(m0 + 8) * N + n]) = r1;
        }
    }
}

// ---------------------------------------------------------------------------
// kernel_launch
// ---------------------------------------------------------------------------
extern "C" void kernel_launch(void* const* d_in, const int* in_sizes, int n_in,
                              void* d_out, int out_size) {
    const float* x = (const float*)d_in[0];
    const int* w32 = (const int*)d_in[1];  // int8 widened to int32
    const float* scale = (const float*)d_in[2];
    float* y = (float*)d_out;

    const int K = K_FIXED;
    const int N = in_sizes[2];      // 11008
    const int M = in_sizes[0] / K;  // 4096

    __half* wh = nullptr;
    cudaGetSymbolAddress((void**)&wh, g_wh);
    __half* xh = nullptr;
    cudaGetSymbolAddress((void**)&xh, g_xh);

    int nw8 = (N * K) / 8;
    convert_w_kernel<<<(nw8 + 255) / 256, 256>>>(w32, wh, nw8);
    int nx8 = (M * K) / 8;
    convert_x_kernel<<<(nx8 + 255) / 256, 256>>>(x, xh, nx8);

    cudaFuncSetAttribute(gemm_f16_kernel,
                         cudaFuncAttributeMaxDynamicSharedMemorySize,
                         SMEM_TOTAL);

    dim3 grid(M / BM, N / BN);  // (32, 86); M fastest -> A L2-resident
    gemm_f16_kernel<<<grid, THREADS, SMEM_TOTAL>>>(xh, wh, scale, y, M, N, K);
}

// round 6
// speedup vs baseline: 1.3568x; 1.1315x over previous
#include <cuda_runtime.h>
#include <cuda_fp16.h>
#include <cstdint>

// ============================================================================
// Int8Linear: y[M,N] = (x[M,K] @ W^T[K,N]) * scale[n], fp32 accum
// M=4096, K=4096, N=11008.  compute_103 feature set (mma.sync + cp.async).
// 128x128x64 tile, 3-stage ring, XOR-128 swizzle, 2 CTAs/SM.
// R6: single barrier per K-iter; B fragments hoisted per iteration (ldsm4
// over k32 pairs); prefetch-after-sync ordering.
// ============================================================================

#define BM 128
#define BN 128
#define BK 64
#define STAGES 3
#define THREADS 256

#define STAGE_BYTES 32768  // A 16KB + B 16KB
#define SMEM_TOTAL (STAGES * STAGE_BYTES)  // 96 KB

#define N_MAX 11008
#define K_FIXED 4096
#define M_MAX 4096

__device__ __half g_wh[(size_t)N_MAX * K_FIXED];
__device__ __half g_xh[(size_t)M_MAX * K_FIXED];

// ---------------------------------------------------------------------------
// W int32 -> fp16 (exact: |w| <= 127)
// ---------------------------------------------------------------------------
__global__ void convert_w_kernel(const int* __restrict__ w,
                                 __half* __restrict__ out, int n8) {
    int i = blockIdx.x * blockDim.x + threadIdx.x;
    if (i >= n8) return;
    int4 a = reinterpret_cast<const int4*>(w)[2 * i];
    int4 b = reinterpret_cast<const int4*>(w)[2 * i + 1];
    __half h[8];
    h[0] = __int2half_rn(a.x); h[1] = __int2half_rn(a.y);
    h[2] = __int2half_rn(a.z); h[3] = __int2half_rn(a.w);
    h[4] = __int2half_rn(b.x); h[5] = __int2half_rn(b.y);
    h[6] = __int2half_rn(b.z); h[7] = __int2half_rn(b.w);
    reinterpret_cast<uint4*>(out)[i] = *reinterpret_cast<uint4*>(h);
}

// ---------------------------------------------------------------------------
// x f32 -> f16 (exact)
// ---------------------------------------------------------------------------
__global__ void convert_x_kernel(const float* __restrict__ x,
                                 __half* __restrict__ out, int n8) {
    int i = blockIdx.x * blockDim.x + threadIdx.x;
    if (i >= n8) return;
    float4 a = reinterpret_cast<const float4*>(x)[2 * i];
    float4 b = reinterpret_cast<const float4*>(x)[2 * i + 1];
    __half h[8];
    h[0] = __float2half_rn(a.x); h[1] = __float2half_rn(a.y);
    h[2] = __float2half_rn(a.z); h[3] = __float2half_rn(a.w);
    h[4] = __float2half_rn(b.x); h[5] = __float2half_rn(b.y);
    h[6] = __float2half_rn(b.z); h[7] = __float2half_rn(b.w);
    reinterpret_cast<uint4*>(out)[i] = *reinterpret_cast<uint4*>(h);
}

// ---------------------------------------------------------------------------
// PTX helpers
// ---------------------------------------------------------------------------
__device__ __forceinline__ uint32_t smem_u32(const void* p) {
    return (uint32_t)__cvta_generic_to_shared(p);
}

__device__ __forceinline__ uint32_t sw128(uint32_t off) {
    return off ^ ((off >> 3) & 0x70);
}

__device__ __forceinline__ void cp_async16(uint32_t s, const void* g) {
    asm volatile("cp.async.cg.shared.global [%0], [%1], 16;\n" ::"r"(s), "l"(g));
}

__device__ __forceinline__ void ldsm4(uint32_t r[4], uint32_t addr) {
    asm volatile("ldmatrix.sync.aligned.m8n8.x4.shared.b16 {%0,%1,%2,%3}, [%4];\n"
                 : "=r"(r[0]), "=r"(r[1]), "=r"(r[2]), "=r"(r[3])
                 : "r"(addr));
}

__device__ __forceinline__ void mma_16816(float c[4], const uint32_t a[4],
                                          const uint32_t b0, const uint32_t b1) {
    asm volatile(
        "mma.sync.aligned.m16n8k16.row.col.f32.f16.f16.f32 "
        "{%0,%1,%2,%3}, {%4,%5,%6,%7}, {%8,%9}, {%0,%1,%2,%3};\n"
        : "+f"(c[0]), "+f"(c[1]), "+f"(c[2]), "+f"(c[3])
        : "r"(a[0]), "r"(a[1]), "r"(a[2]), "r"(a[3]), "r"(b0), "r"(b1));
}

// ---------------------------------------------------------------------------
// Stage loader: A 128x64h + B 128x64h, XOR-128 swizzle
// ---------------------------------------------------------------------------
__device__ __forceinline__ void load_stage(uint32_t baseA, uint32_t baseB,
                                           const __half* __restrict__ Ag,
                                           const __half* __restrict__ Bg,
                                           int K, int k0, int tid) {
#pragma unroll
    for (int t = 0; t < 4; ++t) {
        int ch = tid + t * THREADS;   // 0..1023
        int row = ch >> 3;            // 0..127
        int c16 = ch & 7;             // 16B chunk in 128B row
        uint32_t sw = sw128((uint32_t)(row * 128 + c16 * 16));
        cp_async16(baseA + sw, Ag + (size_t)row * K + k0 + c16 * 8);
        cp_async16(baseB + sw, Bg + (size_t)row * K + k0 + c16 * 8);
    }
}

// ---------------------------------------------------------------------------
// GEMM
// ---------------------------------------------------------------------------
__global__ void __launch_bounds__(THREADS, 2)
gemm_f16_kernel(const __half* __restrict__ A, const __half* __restrict__ Bw,
                const float* __restrict__ scale, float* __restrict__ C,
                int M, int N, int K) {
    extern __shared__ char smem[];
    const uint32_t sb = smem_u32(smem);

    const int tid = threadIdx.x;
    const int lane = tid & 31;
    const int warp = tid >> 5;
    const int warp_m = warp >> 2;  // 0..1 (64 rows)
    const int warp_n = warp & 3;   // 0..3 (32 cols)

    const int bm = blockIdx.x * BM;
    const int bn = blockIdx.y * BN;

    const __half* Ag = A + (size_t)bm * K;
    const __half* Bg = Bw + (size_t)bn * K;

    float acc[4][4][4];
#pragma unroll
    for (int i = 0; i < 4; ++i)
#pragma unroll
        for (int j = 0; j < 4; ++j)
#pragma unroll
            for (int v = 0; v < 4; ++v) acc[i][j][v] = 0.0f;

    const int KITERS = K / BK;  // 64

    // Prologue: stages 0,1
#pragma unroll
    for (int s = 0; s < STAGES - 1; ++s) {
        load_stage(sb + s * STAGE_BYTES, sb + s * STAGE_BYTES + 16384, Ag, Bg,
                   K, s * BK, tid);
        asm volatile("cp.async.commit_group;\n");
    }

    // A ldsm4 lane addressing (validated): rows m16, two k8 byte-halves
    const uint32_t a_off0 =
        (uint32_t)((warp_m * 64 + (lane & 15)) * 128 + ((lane >> 4) << 4));
    // B ldsm4 lane addressing: matrix j = lane>>3 covers kbyte j*16 at fixed
    // n-rows; one ldsm4 = frags for two k16 steps.
    const uint32_t b_off0 =
        (uint32_t)((warp_n * 32 + (lane & 7)) * 128 + ((lane >> 3) << 4));

    for (int it = 0; it < KITERS; ++it) {
        if (it + 1 < KITERS) {
            asm volatile("cp.async.wait_group 1;\n");
        } else {
            asm volatile("cp.async.wait_group 0;\n");
        }
        __syncthreads();  // stage `it` visible; compute `it-1` finished by all

        // Prefetch stage it+2 into the slot consumed at it-1 (safe post-sync)
        int nxt = it + STAGES - 1;
        if (nxt < KITERS) {
            int ns = nxt % STAGES;
            load_stage(sb + ns * STAGE_BYTES, sb + ns * STAGE_BYTES + 16384,
                       Ag, Bg, K, nxt * BK, tid);
        }
        asm volatile("cp.async.commit_group;\n");

        const uint32_t Ast = sb + (it % STAGES) * STAGE_BYTES;
        const uint32_t Bst = Ast + 16384;

        // Hoist ALL B fragments for this iteration: tn x {k0-31, k32-63}
        uint32_t bf[4][2][4];
#pragma unroll
        for (int tn = 0; tn < 4; ++tn)
#pragma unroll
            for (int g = 0; g < 2; ++g)
                ldsm4(bf[tn][g], Bst + sw128(b_off0 + tn * 8 * 128 + g * 64));

#pragma unroll
        for (int ks = 0; ks < 4; ++ks) {
            uint32_t af[4][4];
#pragma unroll
            for (int tm = 0; tm < 4; ++tm)
                ldsm4(af[tm], Ast + sw128(a_off0 + tm * 16 * 128 + ks * 32));
            const int g = ks >> 1;
            const int p = (ks & 1) << 1;
#pragma unroll
            for (int tm = 0; tm < 4; ++tm)
#pragma unroll
                for (int tn = 0; tn < 4; ++tn)
                    mma_16816(acc[tm][tn], af[tm], bf[tn][g][p],
                              bf[tn][g][p + 1]);
        }
    }

    // Epilogue: scale, round through f16, f32 pair stores
    const int c_row = lane >> 2;
    const int c_col = (lane & 3) << 1;

#pragma unroll
    for (int tm = 0; tm < 4; ++tm) {
#pragma unroll
        for (int tn = 0; tn < 4; ++tn) {
            int n = bn + warp_n * 32 + tn * 8 + c_col;
            float s0 = __ldg(scale + n);
            float s1 = __ldg(scale + n + 1);
            int m0 = bm + warp_m * 64 + tm * 16 + c_row;
            float2 r0, r1;
            r0.x = __half2float(__float2half_rn(acc[tm][tn][0] * s0));
            r0.y = __half2float(__float2half_rn(acc[tm][tn][1] * s1));
            r1.x = __half2float(__float2half_rn(acc[tm][tn][2] * s0));
            r1.y = __half2float(__float2half_rn(acc[tm][tn][3] * s1));
            *reinterpret_cast<float2*>(&C[(size_t)m0 * N + n]) = r0;
            *reinterpret_cast<float2*>(&C[(size_t)(m0 + 8) * N + n]) = r1;
        }
    }
}

// ---------------------------------------------------------------------------
// kernel_launch
// ---------------------------------------------------------------------------
extern "C" void kernel_launch(void* const* d_in, const int* in_sizes, int n_in,
                              void* d_out, int out_size) {
    const float* x = (const float*)d_in[0];
    const int* w32 = (const int*)d_in[1];  // int8 widened to int32
    const float* scale = (const float*)d_in[2];
    float* y = (float*)d_out;

    const int K = K_FIXED;
    const int N = in_sizes[2];      // 11008
    const int M = in_sizes[0] / K;  // 4096

    __half* wh = nullptr;
    cudaGetSymbolAddress((void**)&wh, g_wh);
    __half* xh = nullptr;
    cudaGetSymbolAddress((void**)&xh, g_xh);

    int nw8 = (N * K) / 8;
    convert_w_kernel<<<(nw8 + 255) / 256, 256>>>(w32, wh, nw8);
    int nx8 = (M * K) / 8;
    convert_x_kernel<<<(nx8 + 255) / 256, 256>>>(x, xh, nx8);

    cudaFuncSetAttribute(gemm_f16_kernel,
                         cudaFuncAttributeMaxDynamicSharedMemorySize,
                         SMEM_TOTAL);

    dim3 grid(M / BM, N / BN);  // (32, 86); M fastest -> A L2-resident
    gemm_f16_kernel<<<grid, THREADS, SMEM_TOTAL>>>(xh, wh, scale, y, M, N, K);
}